// round 6
// baseline (speedup 1.0000x reference)
#include <cuda_runtime.h>
#include <cuda_fp16.h>
#include <cuda_bf16.h>
#include <cstdint>

#define NMAX 100000
#define EMAX 1200000
#define CSRMAX (NMAX + EMAX)

// ---------------- scratch (device globals; no allocations allowed) ----------
__device__ float   g_h0[NMAX * 64];     // proj output / residual, later reused as h2
__device__ float   g_h1[NMAX * 64];     // layer1 output
__device__ __half2 g_tmp[NMAX * 32];    // W-transformed features (fp16 gather table)
__device__ float   g_byp[NMAX * 3];     // bypass projection
__device__ float   g_dinv[NMAX];
__device__ int     g_deg[NMAX];
__device__ int     g_rowptr[NMAX + 1];
__device__ int     g_cursor[NMAX];
__device__ float2  g_csr[CSRMAX];       // .x = src index (bit-cast), .y = dinv[src]
__device__ int     g_bsum[256];

// ---------------- mma.sync helper (sm_80 baseline PTX — safe on compute_103) -
__device__ __forceinline__ void mma16816(float& d0, float& d1, float& d2, float& d3,
                                         unsigned a0, unsigned a1, unsigned a2, unsigned a3,
                                         unsigned b0, unsigned b1) {
    asm volatile(
        "mma.sync.aligned.m16n8k16.row.col.f32.f16.f16.f32 "
        "{%0,%1,%2,%3}, {%4,%5,%6,%7}, {%8,%9}, {%0,%1,%2,%3};"
        : "+f"(d0), "+f"(d1), "+f"(d2), "+f"(d3)
        : "r"(a0), "r"(a1), "r"(a2), "r"(a3), "r"(b0), "r"(b1));
}

// ---------------- CSR build --------------------------------------------------
__global__ void deg_init_kernel(int* deg, int N) {
    int i = blockIdx.x * blockDim.x + threadIdx.x;
    if (i < N) deg[i] = 1;  // self-loop
}

__global__ void hist_kernel(const int* __restrict__ col, int* deg, int E) {
    int e = blockIdx.x * blockDim.x + threadIdx.x;
    if (e < E) atomicAdd(&deg[col[e]], 1);
}

__global__ void scan1_kernel(const int* __restrict__ deg, int* rowptr, int* bsum, int N) {
    __shared__ int sm[1024];
    int tid = threadIdx.x;
    int i = blockIdx.x * 1024 + tid;
    int v = (i < N) ? deg[i] : 0;
    sm[tid] = v;
    __syncthreads();
    for (int off = 1; off < 1024; off <<= 1) {
        int t = (tid >= off) ? sm[tid - off] : 0;
        __syncthreads();
        sm[tid] += t;
        __syncthreads();
    }
    int incl = sm[tid];
    if (i < N) rowptr[i] = incl - v;
    if (tid == 1023) bsum[blockIdx.x] = incl;
}

__global__ void scan2_kernel(int* bsum, int nb) {
    __shared__ int sm[128];
    int t = threadIdx.x;
    int v = (t < nb) ? bsum[t] : 0;
    sm[t] = v;
    __syncthreads();
    for (int off = 1; off < 128; off <<= 1) {
        int u = (t >= off) ? sm[t - off] : 0;
        __syncthreads();
        sm[t] += u;
        __syncthreads();
    }
    if (t < nb) bsum[t] = sm[t] - v;
}

__global__ void scan3_kernel(const int* __restrict__ deg, int* rowptr,
                             const int* __restrict__ bsum, int* cursor,
                             float* dinv, float2* csr, int N) {
    int i = blockIdx.x * blockDim.x + threadIdx.x;
    if (i >= N) return;
    int rp = rowptr[i] + bsum[i >> 10];
    rowptr[i] = rp;
    cursor[i] = rp + 1;
    float dv = rsqrtf((float)deg[i]);
    dinv[i] = dv;
    csr[rp] = make_float2(__int_as_float(i), dv);
    if (i == N - 1) rowptr[N] = rp + deg[i];
}

__global__ void fill_kernel(const int* __restrict__ row, const int* __restrict__ col,
                            const float* __restrict__ dinv, int* cursor,
                            float2* csr, int E) {
    int e = blockIdx.x * blockDim.x + threadIdx.x;
    if (e >= E) return;
    int d = col[e];
    int pos = atomicAdd(&cursor[d], 1);
    int s = row[e];
    csr[pos] = make_float2(__int_as_float(s), dinv[s]);
}

// ---------------- conv GEMM via mma.sync (K=64), fp16 out -------------------
// out[n][c] = sum_k A[n][k] * W[c][k]; A fp32 -> fp16, fp32 accumulate.
__global__ void __launch_bounds__(128) gemm_mma64_kernel(
    const float* __restrict__ A, const float* __restrict__ W,
    __half2* __restrict__ out, int N)
{
    __shared__ __half Ah[128][72];
    __shared__ __half Ws[64][72];
    int tid = threadIdx.x, wid = tid >> 5, lane = tid & 31;
    int row0 = blockIdx.x * 128;
    int g = lane >> 2, tg = lane & 3;

    for (int l = tid; l < 2048; l += 128) {
        int r = l >> 4, c4 = (l & 15) * 4;
        int n = row0 + r;
        float4 f = (n < N) ? *(const float4*)(A + n * 64 + c4)
                           : make_float4(0.f, 0.f, 0.f, 0.f);
        __half2* dst = (__half2*)&Ah[r][c4];
        dst[0] = __floats2half2_rn(f.x, f.y);
        dst[1] = __floats2half2_rn(f.z, f.w);
    }
    for (int l = tid; l < 1024; l += 128) {
        int r = l >> 4, c4 = (l & 15) * 4;
        float4 f = *(const float4*)(W + r * 64 + c4);
        __half2* dst = (__half2*)&Ws[r][c4];
        dst[0] = __floats2half2_rn(f.x, f.y);
        dst[1] = __floats2half2_rn(f.z, f.w);
    }
    __syncthreads();

    float acc[2][8][4];
#pragma unroll
    for (int rt = 0; rt < 2; ++rt)
#pragma unroll
        for (int ct = 0; ct < 8; ++ct)
#pragma unroll
            for (int q = 0; q < 4; ++q) acc[rt][ct][q] = 0.f;

#pragma unroll
    for (int ks = 0; ks < 4; ++ks) {
        int kb = ks * 16;
        unsigned a[2][4];
#pragma unroll
        for (int rt = 0; rt < 2; ++rt) {
            int r = wid * 32 + rt * 16;
            a[rt][0] = *(const unsigned*)&Ah[r + g][kb + tg * 2];
            a[rt][1] = *(const unsigned*)&Ah[r + g + 8][kb + tg * 2];
            a[rt][2] = *(const unsigned*)&Ah[r + g][kb + 8 + tg * 2];
            a[rt][3] = *(const unsigned*)&Ah[r + g + 8][kb + 8 + tg * 2];
        }
#pragma unroll
        for (int ct = 0; ct < 8; ++ct) {
            unsigned b0 = *(const unsigned*)&Ws[ct * 8 + g][kb + tg * 2];
            unsigned b1 = *(const unsigned*)&Ws[ct * 8 + g][kb + 8 + tg * 2];
#pragma unroll
            for (int rt = 0; rt < 2; ++rt)
                mma16816(acc[rt][ct][0], acc[rt][ct][1], acc[rt][ct][2], acc[rt][ct][3],
                         a[rt][0], a[rt][1], a[rt][2], a[rt][3], b0, b1);
        }
    }

#pragma unroll
    for (int rt = 0; rt < 2; ++rt) {
        int nA = row0 + wid * 32 + rt * 16 + g;
        int nB = nA + 8;
#pragma unroll
        for (int ct = 0; ct < 8; ++ct) {
            int hc = ct * 4 + tg;
            if (nA < N) out[nA * 32 + hc] = __floats2half2_rn(acc[rt][ct][0], acc[rt][ct][1]);
            if (nB < N) out[nB * 32 + hc] = __floats2half2_rn(acc[rt][ct][2], acc[rt][ct][3]);
        }
    }
}

// ---------------- proj GEMM via mma.sync (K=128, 2 chunks) + bias + bypass --
__global__ void __launch_bounds__(128) proj_mma_kernel(
    const float* __restrict__ x, const float* __restrict__ Wp,
    const float* __restrict__ bp, const float* __restrict__ Wb,
    const float* __restrict__ bb, float* __restrict__ h0,
    float* __restrict__ byp, int N)
{
    __shared__ __half Ah[128][72];
    __shared__ __half Ws[64][72];
    __shared__ float sBy[3][64];
    int tid = threadIdx.x, wid = tid >> 5, lane = tid & 31;
    int row0 = blockIdx.x * 128;
    int g = lane >> 2, tg = lane & 3;

    float acc[2][8][4];
#pragma unroll
    for (int rt = 0; rt < 2; ++rt)
#pragma unroll
        for (int ct = 0; ct < 8; ++ct)
#pragma unroll
            for (int q = 0; q < 4; ++q) acc[rt][ct][q] = 0.f;
    float bacc[3] = {0.f, 0.f, 0.f};

    for (int kc = 0; kc < 2; ++kc) {
        int kb0 = kc * 64;
        for (int l = tid; l < 2048; l += 128) {
            int r = l >> 4, c4 = (l & 15) * 4;
            int n = row0 + r;
            float4 f = (n < N) ? *(const float4*)(x + n * 128 + kb0 + c4)
                               : make_float4(0.f, 0.f, 0.f, 0.f);
            __half2* dst = (__half2*)&Ah[r][c4];
            dst[0] = __floats2half2_rn(f.x, f.y);
            dst[1] = __floats2half2_rn(f.z, f.w);
        }
        for (int l = tid; l < 1024; l += 128) {
            int r = l >> 4, c4 = (l & 15) * 4;
            float4 f = *(const float4*)(Wp + r * 128 + kb0 + c4);
            __half2* dst = (__half2*)&Ws[r][c4];
            dst[0] = __floats2half2_rn(f.x, f.y);
            dst[1] = __floats2half2_rn(f.z, f.w);
        }
        for (int l = tid; l < 192; l += 128)
            sBy[l >> 6][l & 63] = Wb[(l >> 6) * 128 + kb0 + (l & 63)];
        __syncthreads();

#pragma unroll
        for (int ks = 0; ks < 4; ++ks) {
            int kb = ks * 16;
            unsigned a[2][4];
#pragma unroll
            for (int rt = 0; rt < 2; ++rt) {
                int r = wid * 32 + rt * 16;
                a[rt][0] = *(const unsigned*)&Ah[r + g][kb + tg * 2];
                a[rt][1] = *(const unsigned*)&Ah[r + g + 8][kb + tg * 2];
                a[rt][2] = *(const unsigned*)&Ah[r + g][kb + 8 + tg * 2];
                a[rt][3] = *(const unsigned*)&Ah[r + g + 8][kb + 8 + tg * 2];
            }
#pragma unroll
            for (int ct = 0; ct < 8; ++ct) {
                unsigned b0 = *(const unsigned*)&Ws[ct * 8 + g][kb + tg * 2];
                unsigned b1 = *(const unsigned*)&Ws[ct * 8 + g][kb + 8 + tg * 2];
#pragma unroll
                for (int rt = 0; rt < 2; ++rt)
                    mma16816(acc[rt][ct][0], acc[rt][ct][1], acc[rt][ct][2], acc[rt][ct][3],
                             a[rt][0], a[rt][1], a[rt][2], a[rt][3], b0, b1);
            }
        }

        // bypass partials: thread = row, dot over this 64-chunk from smem
        {
            int r = tid;
            const __half2* arow = (const __half2*)&Ah[r][0];
            float s0 = 0.f, s1 = 0.f, s2 = 0.f;
#pragma unroll 8
            for (int c = 0; c < 32; ++c) {
                float2 f = __half22float2(arow[c]);
                s0 += f.x * sBy[0][2 * c] + f.y * sBy[0][2 * c + 1];
                s1 += f.x * sBy[1][2 * c] + f.y * sBy[1][2 * c + 1];
                s2 += f.x * sBy[2][2 * c] + f.y * sBy[2][2 * c + 1];
            }
            bacc[0] += s0; bacc[1] += s1; bacc[2] += s2;
        }
        __syncthreads();
    }

#pragma unroll
    for (int rt = 0; rt < 2; ++rt) {
        int nA = row0 + wid * 32 + rt * 16 + g;
        int nB = nA + 8;
#pragma unroll
        for (int ct = 0; ct < 8; ++ct) {
            int c = ct * 8 + tg * 2;
            if (nA < N) {
                float2 v = make_float2(acc[rt][ct][0] + bp[c], acc[rt][ct][1] + bp[c + 1]);
                *(float2*)(h0 + nA * 64 + c) = v;
            }
            if (nB < N) {
                float2 v = make_float2(acc[rt][ct][2] + bp[c], acc[rt][ct][3] + bp[c + 1]);
                *(float2*)(h0 + nB * 64 + c) = v;
            }
        }
    }
    {
        int nr = row0 + tid;
        if (nr < N) {
            byp[nr * 3 + 0] = bacc[0] + bb[0];
            byp[nr * 3 + 1] = bacc[1] + bb[1];
            byp[nr * 3 + 2] = bacc[2] + bb[2];
        }
    }
}

// ---------------- aggregation (warp per destination node) -------------------
__global__ void __launch_bounds__(256) agg_kernel(
    const __half2* __restrict__ tmp, const float2* __restrict__ csr,
    const int* __restrict__ rowptr, const float* __restrict__ dinv,
    const float* __restrict__ convb, const float* __restrict__ bng,
    const float* __restrict__ bnb, const float* __restrict__ resid,
    float* __restrict__ outh, const float* __restrict__ headW,
    const float* __restrict__ headb, const float* __restrict__ byp,
    float* __restrict__ out, int N, int mode)
{
    int gt = blockIdx.x * blockDim.x + threadIdx.x;
    int v = gt >> 5;
    int lane = gt & 31;
    if (v >= N) return;

    int s = rowptr[v];
    int e = rowptr[v + 1];
    float ax = 0.f, ay = 0.f;
    int p = s;
    for (; p + 1 < e; p += 2) {
        float2 e0 = csr[p];
        float2 e1 = csr[p + 1];
        int s0 = __float_as_int(e0.x);
        int s1 = __float_as_int(e1.x);
        float2 h0v = __half22float2(tmp[s0 * 32 + lane]);
        float2 h1v = __half22float2(tmp[s1 * 32 + lane]);
        ax = fmaf(e0.y, h0v.x, ax);
        ay = fmaf(e0.y, h0v.y, ay);
        ax = fmaf(e1.y, h1v.x, ax);
        ay = fmaf(e1.y, h1v.y, ay);
    }
    if (p < e) {
        float2 e0 = csr[p];
        int s0 = __float_as_int(e0.x);
        float2 h0v = __half22float2(tmp[s0 * 32 + lane]);
        ax = fmaf(e0.y, h0v.x, ax);
        ay = fmaf(e0.y, h0v.y, ay);
    }

    float dv = dinv[v];
    int c0 = lane * 2;
    const float bninv = rsqrtf(1.0f + 1e-5f);
    float v0 = fmaf(fmaf(ax, dv, convb[c0]),     bng[c0] * bninv,     bnb[c0]);
    float v1 = fmaf(fmaf(ay, dv, convb[c0 + 1]), bng[c0 + 1] * bninv, bnb[c0 + 1]);
    v0 = fmaxf(v0, 0.f);
    v1 = fmaxf(v1, 0.f);

    if (mode == 0) {
        float2 r = ((const float2*)resid)[v * 32 + lane];
        float2 o;
        o.x = v0 + r.x;
        o.y = v1 + r.y;
        ((float2*)outh)[v * 32 + lane] = o;
    } else {
        float p0 = v0 * headW[c0]       + v1 * headW[c0 + 1];
        float p1 = v0 * headW[67 + c0]  + v1 * headW[67 + c0 + 1];
        float p2 = v0 * headW[134 + c0] + v1 * headW[134 + c0 + 1];
#pragma unroll
        for (int o = 16; o > 0; o >>= 1) {
            p0 += __shfl_xor_sync(0xffffffffu, p0, o);
            p1 += __shfl_xor_sync(0xffffffffu, p1, o);
            p2 += __shfl_xor_sync(0xffffffffu, p2, o);
        }
        if (lane == 0) {
            float b0 = byp[v * 3], b1 = byp[v * 3 + 1], b2 = byp[v * 3 + 2];
            p0 += headW[64] * b0 + headW[65] * b1 + headW[66] * b2 + headb[0];
            p1 += headW[67 + 64] * b0 + headW[67 + 65] * b1 + headW[67 + 66] * b2 + headb[1];
            p2 += headW[134 + 64] * b0 + headW[134 + 65] * b1 + headW[134 + 66] * b2 + headb[2];
            float kappa = fminf(fmaxf(p0 * 5.f + 2.5f, 0.2f), 10.f);
            float tau   = fminf(fmaxf(p2 + 0.5f, 0.05f), 2.f);
            out[v * 3]     = kappa;
            out[v * 3 + 1] = p1;
            out[v * 3 + 2] = tau;
        }
    }
}

// ---------------- launch -----------------------------------------------------
extern "C" void kernel_launch(void* const* d_in, const int* in_sizes, int n_in,
                              void* d_out, int out_size) {
    const float* x      = (const float*)d_in[0];
    const int*   ei     = (const int*)d_in[1];
    const float* projW  = (const float*)d_in[2];
    const float* projB  = (const float*)d_in[3];
    const float* conv1W = (const float*)d_in[4];
    const float* conv1B = (const float*)d_in[5];
    const float* bn1g   = (const float*)d_in[6];
    const float* bn1b   = (const float*)d_in[7];
    const float* conv2W = (const float*)d_in[8];
    const float* conv2B = (const float*)d_in[9];
    const float* bn2g   = (const float*)d_in[10];
    const float* bn2b   = (const float*)d_in[11];
    const float* conv3W = (const float*)d_in[12];
    const float* conv3B = (const float*)d_in[13];
    const float* bn3g   = (const float*)d_in[14];
    const float* bn3b   = (const float*)d_in[15];
    const float* bypW   = (const float*)d_in[16];
    const float* bypB   = (const float*)d_in[17];
    const float* headW  = (const float*)d_in[18];
    const float* headB  = (const float*)d_in[19];
    float* out = (float*)d_out;

    int N = in_sizes[0] / 128;
    int E = in_sizes[1] / 2;
    const int* row = ei;
    const int* col = ei + E;

    float *p_h0, *p_h1, *p_byp, *p_dinv;
    __half2* p_tmp;
    int *p_deg, *p_rowptr, *p_cursor, *p_bsum;
    float2* p_csr;
    cudaGetSymbolAddress((void**)&p_h0, g_h0);
    cudaGetSymbolAddress((void**)&p_h1, g_h1);
    cudaGetSymbolAddress((void**)&p_tmp, g_tmp);
    cudaGetSymbolAddress((void**)&p_byp, g_byp);
    cudaGetSymbolAddress((void**)&p_dinv, g_dinv);
    cudaGetSymbolAddress((void**)&p_deg, g_deg);
    cudaGetSymbolAddress((void**)&p_rowptr, g_rowptr);
    cudaGetSymbolAddress((void**)&p_cursor, g_cursor);
    cudaGetSymbolAddress((void**)&p_bsum, g_bsum);
    cudaGetSymbolAddress((void**)&p_csr, g_csr);

    int nb = (N + 1023) / 1024;

    deg_init_kernel<<<(N + 255) / 256, 256>>>(p_deg, N);
    hist_kernel<<<(E + 255) / 256, 256>>>(col, p_deg, E);
    scan1_kernel<<<nb, 1024>>>(p_deg, p_rowptr, p_bsum, N);
    scan2_kernel<<<1, 128>>>(p_bsum, nb);
    scan3_kernel<<<(N + 255) / 256, 256>>>(p_deg, p_rowptr, p_bsum, p_cursor, p_dinv, p_csr, N);
    fill_kernel<<<(E + 255) / 256, 256>>>(row, col, p_dinv, p_cursor, p_csr, E);

    int mma_blocks = (N + 127) / 128;
    int agg_blocks = (N * 32 + 255) / 256;

    // h0 = x @ projW.T + projB ; byp = x @ bypW.T + bypB
    proj_mma_kernel<<<mma_blocks, 128>>>(x, projW, projB, bypW, bypB, p_h0, p_byp, N);

    // layer 1: h1 = relu(bn(agg(h0 @ W1.T) + b1)) + h0
    gemm_mma64_kernel<<<mma_blocks, 128>>>(p_h0, conv1W, p_tmp, N);
    agg_kernel<<<agg_blocks, 256>>>(p_tmp, p_csr, p_rowptr, p_dinv,
                                    conv1B, bn1g, bn1b, p_h0, p_h1,
                                    nullptr, nullptr, nullptr, nullptr, N, 0);

    // layer 2 (result into g_h0)
    gemm_mma64_kernel<<<mma_blocks, 128>>>(p_h1, conv2W, p_tmp, N);
    agg_kernel<<<agg_blocks, 256>>>(p_tmp, p_csr, p_rowptr, p_dinv,
                                    conv2B, bn2g, bn2b, p_h1, p_h0,
                                    nullptr, nullptr, nullptr, nullptr, N, 0);

    // layer 3 + head fused
    gemm_mma64_kernel<<<mma_blocks, 128>>>(p_h0, conv3W, p_tmp, N);
    agg_kernel<<<agg_blocks, 256>>>(p_tmp, p_csr, p_rowptr, p_dinv,
                                    conv3B, bn3g, bn3b, nullptr, nullptr,
                                    headW, headB, p_byp, out, N, 1);
}

// round 7
// speedup vs baseline: 1.2718x; 1.2718x over previous
#include <cuda_runtime.h>
#include <cuda_fp16.h>
#include <cuda_bf16.h>

#define NMAX 100000
#define EMAX 1200000
#define CSRMAX (NMAX + EMAX)

// ---------------- scratch (device globals; no allocations allowed) ----------
__device__ float   g_h0[NMAX * 64];     // proj output / residual, later reused as h2
__device__ float   g_h1[NMAX * 64];     // layer1 output
__device__ __half2 g_tmp[NMAX * 32];    // W-transformed features (fp16 gather table)
__device__ float   g_byp[NMAX * 3];     // bypass projection
__device__ float   g_dinv[NMAX];
__device__ int     g_deg[NMAX];
__device__ int     g_rowptr[NMAX + 1];
__device__ int     g_cursor[NMAX];
__device__ float2  g_csr[CSRMAX];       // .x = src index (bit-cast), .y = dinv[src]
__device__ int     g_bsum[256];

// ---------------- f32x2 helpers -----------------------------------------------
__device__ __forceinline__ void ffma2(unsigned long long& d,
                                      unsigned long long a,
                                      unsigned long long b) {
    asm("fma.rn.f32x2 %0, %1, %2, %0;" : "+l"(d) : "l"(a), "l"(b));
}
__device__ __forceinline__ unsigned long long dup2(float x) {
    unsigned long long r;
    unsigned u = __float_as_uint(x);
    asm("mov.b64 %0, {%1, %1};" : "=l"(r) : "r"(u));
    return r;
}
__device__ __forceinline__ float lo32(unsigned long long v) {
    return __uint_as_float((unsigned)(v & 0xffffffffull));
}
__device__ __forceinline__ float hi32(unsigned long long v) {
    return __uint_as_float((unsigned)(v >> 32));
}

// ---------------- CSR build --------------------------------------------------
__global__ void deg_init_kernel(int* deg, int N) {
    int i = blockIdx.x * blockDim.x + threadIdx.x;
    if (i < N) deg[i] = 1;  // self-loop
}

__global__ void hist_kernel(const int* __restrict__ col, int* deg, int E) {
    int e = blockIdx.x * blockDim.x + threadIdx.x;
    if (e < E) atomicAdd(&deg[col[e]], 1);
}

__global__ void scan1_kernel(const int* __restrict__ deg, int* rowptr, int* bsum, int N) {
    __shared__ int sm[1024];
    int tid = threadIdx.x;
    int i = blockIdx.x * 1024 + tid;
    int v = (i < N) ? deg[i] : 0;
    sm[tid] = v;
    __syncthreads();
    for (int off = 1; off < 1024; off <<= 1) {
        int t = (tid >= off) ? sm[tid - off] : 0;
        __syncthreads();
        sm[tid] += t;
        __syncthreads();
    }
    int incl = sm[tid];
    if (i < N) rowptr[i] = incl - v;  // exclusive within block
    if (tid == 1023) bsum[blockIdx.x] = incl;
}

// parallel exclusive scan of block sums (nb <= 128)
__global__ void scan2_kernel(int* bsum, int nb) {
    __shared__ int sm[128];
    int t = threadIdx.x;
    int v = (t < nb) ? bsum[t] : 0;
    sm[t] = v;
    __syncthreads();
    for (int off = 1; off < 128; off <<= 1) {
        int u = (t >= off) ? sm[t - off] : 0;
        __syncthreads();
        sm[t] += u;
        __syncthreads();
    }
    if (t < nb) bsum[t] = sm[t] - v;
}

__global__ void scan3_kernel(const int* __restrict__ deg, int* rowptr,
                             const int* __restrict__ bsum, int* cursor,
                             float* dinv, float2* csr, int N) {
    int i = blockIdx.x * blockDim.x + threadIdx.x;
    if (i >= N) return;
    int rp = rowptr[i] + bsum[i >> 10];
    rowptr[i] = rp;
    cursor[i] = rp + 1;  // slot rp reserved for self-loop
    float dv = rsqrtf((float)deg[i]);
    dinv[i] = dv;
    csr[rp] = make_float2(__int_as_float(i), dv);
    if (i == N - 1) rowptr[N] = rp + deg[i];
}

__global__ void fill_kernel(const int* __restrict__ row, const int* __restrict__ col,
                            const float* __restrict__ dinv, int* cursor,
                            float2* csr, int E) {
    int e = blockIdx.x * blockDim.x + threadIdx.x;
    if (e >= E) return;
    int d = col[e];
    int pos = atomicAdd(&cursor[d], 1);
    int s = row[e];
    csr[pos] = make_float2(__int_as_float(s), dinv[s]);
}

// ---------------- 64x64 GEMM (FFMA2), fp16 output ---------------------------
__global__ void __launch_bounds__(128) gemm64h_kernel(
    const float* __restrict__ A, const float* __restrict__ W,
    __half2* __restrict__ out, int N)
{
    __shared__ float Xs[64][65];
    __shared__ float Ws[64][66];   // transposed: Ws[k][c]
    int tid = threadIdx.x;
    int row0 = blockIdx.x * 64;
    int tr  = tid >> 3;            // 0..15
    int tc2 = (tid & 7) * 2;       // even col base 0..14

    for (int l = tid; l < 1024; l += 128) {
        int r = l >> 4, k4 = (l & 15) * 4;
        int n = row0 + r;
        float4 xv = make_float4(0.f, 0.f, 0.f, 0.f);
        if (n < N) xv = *(const float4*)(A + n * 64 + k4);
        Xs[r][k4] = xv.x; Xs[r][k4 + 1] = xv.y; Xs[r][k4 + 2] = xv.z; Xs[r][k4 + 3] = xv.w;
        float4 wv = *(const float4*)(W + r * 64 + k4);
        Ws[k4][r] = wv.x; Ws[k4 + 1][r] = wv.y; Ws[k4 + 2][r] = wv.z; Ws[k4 + 3][r] = wv.w;
    }
    __syncthreads();

    unsigned long long acc[4][4];
#pragma unroll
    for (int i = 0; i < 4; ++i)
#pragma unroll
        for (int j = 0; j < 4; ++j) acc[i][j] = 0ull;

#pragma unroll 4
    for (int k = 0; k < 64; ++k) {
        unsigned long long aa[4], wv[4];
#pragma unroll
        for (int i = 0; i < 4; ++i) aa[i] = dup2(Xs[tr + i * 16][k]);
#pragma unroll
        for (int j = 0; j < 4; ++j)
            wv[j] = *(const unsigned long long*)&Ws[k][tc2 + 16 * j];
#pragma unroll
        for (int i = 0; i < 4; ++i)
#pragma unroll
            for (int j = 0; j < 4; ++j) ffma2(acc[i][j], aa[i], wv[j]);
    }

#pragma unroll
    for (int i = 0; i < 4; ++i) {
        int n = row0 + tr + i * 16;
        if (n < N) {
#pragma unroll
            for (int j = 0; j < 4; ++j) {
                float2 v = make_float2(lo32(acc[i][j]), hi32(acc[i][j]));
                out[n * 32 + (tc2 >> 1) + 8 * j] = __float22half2_rn(v);
            }
        }
    }
}

// ---------------- proj GEMM (K=128, +bias) fused with bypass ----------------
__global__ void __launch_bounds__(128) gemm_proj_kernel(
    const float* __restrict__ x, const float* __restrict__ Wp,
    const float* __restrict__ bp, const float* __restrict__ Wb,
    const float* __restrict__ bb, float* __restrict__ h0,
    float* __restrict__ byp, int N)
{
    __shared__ float Xs[64][65];
    __shared__ float Ws[64][66];   // transposed per chunk: Ws[k][c]
    __shared__ float Bs[3][65];
    int tid = threadIdx.x;
    int row0 = blockIdx.x * 64;
    int tr  = tid >> 3;
    int tc2 = (tid & 7) * 2;

    unsigned long long acc[4][4];
    float bacc[4] = {0.f, 0.f, 0.f, 0.f};
#pragma unroll
    for (int i = 0; i < 4; ++i)
#pragma unroll
        for (int j = 0; j < 4; ++j) acc[i][j] = 0ull;

    for (int kc = 0; kc < 2; ++kc) {
        int kbase = kc * 64;
        for (int l = tid; l < 1024; l += 128) {
            int r = l >> 4, k4 = (l & 15) * 4;
            int n = row0 + r;
            float4 xv = make_float4(0.f, 0.f, 0.f, 0.f);
            if (n < N) xv = *(const float4*)(x + n * 128 + kbase + k4);
            Xs[r][k4] = xv.x; Xs[r][k4 + 1] = xv.y; Xs[r][k4 + 2] = xv.z; Xs[r][k4 + 3] = xv.w;
            float4 wv = *(const float4*)(Wp + r * 128 + kbase + k4);
            Ws[k4][r] = wv.x; Ws[k4 + 1][r] = wv.y; Ws[k4 + 2][r] = wv.z; Ws[k4 + 3][r] = wv.w;
        }
        for (int l = tid; l < 192; l += 128)
            Bs[l >> 6][l & 63] = Wb[(l >> 6) * 128 + kbase + (l & 63)];
        __syncthreads();

        int tc = tid & 7;
#pragma unroll 4
        for (int k = 0; k < 64; ++k) {
            float a_s[4];
            unsigned long long aa[4], wv[4];
#pragma unroll
            for (int i = 0; i < 4; ++i) { a_s[i] = Xs[tr + i * 16][k]; aa[i] = dup2(a_s[i]); }
#pragma unroll
            for (int j = 0; j < 4; ++j)
                wv[j] = *(const unsigned long long*)&Ws[k][tc2 + 16 * j];
#pragma unroll
            for (int i = 0; i < 4; ++i)
#pragma unroll
                for (int j = 0; j < 4; ++j) ffma2(acc[i][j], aa[i], wv[j]);
            if (tc < 3) {
                float bw = Bs[tc][k];
#pragma unroll
                for (int i = 0; i < 4; ++i) bacc[i] = fmaf(a_s[i], bw, bacc[i]);
            }
        }
        __syncthreads();
    }

    int tc = tid & 7;
#pragma unroll
    for (int i = 0; i < 4; ++i) {
        int n = row0 + tr + i * 16;
        if (n < N) {
#pragma unroll
            for (int j = 0; j < 4; ++j) {
                int c = tc2 + 16 * j;
                float2 v;
                v.x = lo32(acc[i][j]) + bp[c];
                v.y = hi32(acc[i][j]) + bp[c + 1];
                *(float2*)(h0 + n * 64 + c) = v;
            }
            if (tc < 3) byp[n * 3 + tc] = bacc[i] + bb[tc];
        }
    }
}

// ---------------- aggregation (warp per node, half-warp per edge stream) ----
// Each 16-lane half processes alternating edges; lane loads uint2 = 4 channels.
// mode 0: outh = relu(bn(agg + conv_b)) + resid
// mode 1: head fused -> out (N x 3)
__global__ void __launch_bounds__(256) agg_kernel(
    const __half2* __restrict__ tmp, const float2* __restrict__ csr,
    const int* __restrict__ rowptr, const float* __restrict__ dinv,
    const float* __restrict__ convb, const float* __restrict__ bng,
    const float* __restrict__ bnb, const float* __restrict__ resid,
    float* __restrict__ outh, const float* __restrict__ headW,
    const float* __restrict__ headb, const float* __restrict__ byp,
    float* __restrict__ out, int N, int mode)
{
    int gt = blockIdx.x * blockDim.x + threadIdx.x;
    int v = gt >> 5;
    int lane = gt & 31;
    if (v >= N) return;
    int half = lane >> 4;
    int sub  = lane & 15;

    const uint2* hp = (const uint2*)tmp;   // 16 uint2 per row = 64 channels
    int s = rowptr[v];
    int e = rowptr[v + 1];

    float a0 = 0.f, a1 = 0.f, a2 = 0.f, a3 = 0.f;
    int p = s + half;
    for (; p + 2 < e; p += 4) {
        float2 e0 = csr[p];
        float2 e1 = csr[p + 2];
        int s0 = __float_as_int(e0.x);
        int s1 = __float_as_int(e1.x);
        uint2 r0 = hp[s0 * 16 + sub];
        uint2 r1 = hp[s1 * 16 + sub];
        float2 f00 = __half22float2(*(__half2*)&r0.x);
        float2 f01 = __half22float2(*(__half2*)&r0.y);
        float2 f10 = __half22float2(*(__half2*)&r1.x);
        float2 f11 = __half22float2(*(__half2*)&r1.y);
        a0 = fmaf(e0.y, f00.x, a0); a1 = fmaf(e0.y, f00.y, a1);
        a2 = fmaf(e0.y, f01.x, a2); a3 = fmaf(e0.y, f01.y, a3);
        a0 = fmaf(e1.y, f10.x, a0); a1 = fmaf(e1.y, f10.y, a1);
        a2 = fmaf(e1.y, f11.x, a2); a3 = fmaf(e1.y, f11.y, a3);
    }
    if (p < e) {
        float2 e0 = csr[p];
        int s0 = __float_as_int(e0.x);
        uint2 r0 = hp[s0 * 16 + sub];
        float2 f00 = __half22float2(*(__half2*)&r0.x);
        float2 f01 = __half22float2(*(__half2*)&r0.y);
        a0 = fmaf(e0.y, f00.x, a0); a1 = fmaf(e0.y, f00.y, a1);
        a2 = fmaf(e0.y, f01.x, a2); a3 = fmaf(e0.y, f01.y, a3);
    }
    // combine halves: lanes s and s+16 both end up with the full sum
    a0 += __shfl_xor_sync(0xffffffffu, a0, 16);
    a1 += __shfl_xor_sync(0xffffffffu, a1, 16);
    a2 += __shfl_xor_sync(0xffffffffu, a2, 16);
    a3 += __shfl_xor_sync(0xffffffffu, a3, 16);

    float dv = dinv[v];
    const float bninv = rsqrtf(1.0f + 1e-5f);

    if (mode == 0) {
        if (half == 0) {
            int c = sub * 4;
            float4 cb = *(const float4*)(convb + c);
            float4 bg = *(const float4*)(bng + c);
            float4 bo = *(const float4*)(bnb + c);
            float4 r  = *(const float4*)(resid + v * 64 + c);
            float4 o;
            o.x = fmaxf(fmaf(fmaf(a0, dv, cb.x), bg.x * bninv, bo.x), 0.f) + r.x;
            o.y = fmaxf(fmaf(fmaf(a1, dv, cb.y), bg.y * bninv, bo.y), 0.f) + r.y;
            o.z = fmaxf(fmaf(fmaf(a2, dv, cb.z), bg.z * bninv, bo.z), 0.f) + r.z;
            o.w = fmaxf(fmaf(fmaf(a3, dv, cb.w), bg.w * bninv, bo.w), 0.f) + r.w;
            *(float4*)(outh + v * 64 + c) = o;
        }
    } else {
        float p0 = 0.f, p1 = 0.f, p2 = 0.f;
        if (half == 0) {
            int c = sub * 4;
            float4 cb = *(const float4*)(convb + c);
            float4 bg = *(const float4*)(bng + c);
            float4 bo = *(const float4*)(bnb + c);
            float v0 = fmaxf(fmaf(fmaf(a0, dv, cb.x), bg.x * bninv, bo.x), 0.f);
            float v1 = fmaxf(fmaf(fmaf(a1, dv, cb.y), bg.y * bninv, bo.y), 0.f);
            float v2 = fmaxf(fmaf(fmaf(a2, dv, cb.z), bg.z * bninv, bo.z), 0.f);
            float v3 = fmaxf(fmaf(fmaf(a3, dv, cb.w), bg.w * bninv, bo.w), 0.f);
            p0 = v0 * headW[c]       + v1 * headW[c + 1]       + v2 * headW[c + 2]       + v3 * headW[c + 3];
            p1 = v0 * headW[67 + c]  + v1 * headW[67 + c + 1]  + v2 * headW[67 + c + 2]  + v3 * headW[67 + c + 3];
            p2 = v0 * headW[134 + c] + v1 * headW[134 + c + 1] + v2 * headW[134 + c + 2] + v3 * headW[134 + c + 3];
        }
#pragma unroll
        for (int o = 8; o > 0; o >>= 1) {
            p0 += __shfl_xor_sync(0xffffffffu, p0, o);
            p1 += __shfl_xor_sync(0xffffffffu, p1, o);
            p2 += __shfl_xor_sync(0xffffffffu, p2, o);
        }
        if (lane == 0) {
            float b0 = byp[v * 3], b1 = byp[v * 3 + 1], b2 = byp[v * 3 + 2];
            p0 += headW[64] * b0 + headW[65] * b1 + headW[66] * b2 + headb[0];
            p1 += headW[67 + 64] * b0 + headW[67 + 65] * b1 + headW[67 + 66] * b2 + headb[1];
            p2 += headW[134 + 64] * b0 + headW[134 + 65] * b1 + headW[134 + 66] * b2 + headb[2];
            float kappa = fminf(fmaxf(p0 * 5.f + 2.5f, 0.2f), 10.f);
            float tau   = fminf(fmaxf(p2 + 0.5f, 0.05f), 2.f);
            out[v * 3]     = kappa;
            out[v * 3 + 1] = p1;
            out[v * 3 + 2] = tau;
        }
    }
}

// ---------------- launch -----------------------------------------------------
extern "C" void kernel_launch(void* const* d_in, const int* in_sizes, int n_in,
                              void* d_out, int out_size) {
    const float* x      = (const float*)d_in[0];
    const int*   ei     = (const int*)d_in[1];
    const float* projW  = (const float*)d_in[2];
    const float* projB  = (const float*)d_in[3];
    const float* conv1W = (const float*)d_in[4];
    const float* conv1B = (const float*)d_in[5];
    const float* bn1g   = (const float*)d_in[6];
    const float* bn1b   = (const float*)d_in[7];
    const float* conv2W = (const float*)d_in[8];
    const float* conv2B = (const float*)d_in[9];
    const float* bn2g   = (const float*)d_in[10];
    const float* bn2b   = (const float*)d_in[11];
    const float* conv3W = (const float*)d_in[12];
    const float* conv3B = (const float*)d_in[13];
    const float* bn3g   = (const float*)d_in[14];
    const float* bn3b   = (const float*)d_in[15];
    const float* bypW   = (const float*)d_in[16];
    const float* bypB   = (const float*)d_in[17];
    const float* headW  = (const float*)d_in[18];
    const float* headB  = (const float*)d_in[19];
    float* out = (float*)d_out;

    int N = in_sizes[0] / 128;
    int E = in_sizes[1] / 2;
    const int* row = ei;
    const int* col = ei + E;

    float *p_h0, *p_h1, *p_byp, *p_dinv;
    __half2* p_tmp;
    int *p_deg, *p_rowptr, *p_cursor, *p_bsum;
    float2* p_csr;
    cudaGetSymbolAddress((void**)&p_h0, g_h0);
    cudaGetSymbolAddress((void**)&p_h1, g_h1);
    cudaGetSymbolAddress((void**)&p_tmp, g_tmp);
    cudaGetSymbolAddress((void**)&p_byp, g_byp);
    cudaGetSymbolAddress((void**)&p_dinv, g_dinv);
    cudaGetSymbolAddress((void**)&p_deg, g_deg);
    cudaGetSymbolAddress((void**)&p_rowptr, g_rowptr);
    cudaGetSymbolAddress((void**)&p_cursor, g_cursor);
    cudaGetSymbolAddress((void**)&p_bsum, g_bsum);
    cudaGetSymbolAddress((void**)&p_csr, g_csr);

    int nb = (N + 1023) / 1024;

    deg_init_kernel<<<(N + 255) / 256, 256>>>(p_deg, N);
    hist_kernel<<<(E + 255) / 256, 256>>>(col, p_deg, E);
    scan1_kernel<<<nb, 1024>>>(p_deg, p_rowptr, p_bsum, N);
    scan2_kernel<<<1, 128>>>(p_bsum, nb);
    scan3_kernel<<<(N + 255) / 256, 256>>>(p_deg, p_rowptr, p_bsum, p_cursor, p_dinv, p_csr, N);
    fill_kernel<<<(E + 255) / 256, 256>>>(row, col, p_dinv, p_cursor, p_csr, E);

    int gemm_blocks = (N + 63) / 64;
    int agg_blocks = (N * 32 + 255) / 256;

    // h0 = x @ projW.T + projB ; byp = x @ bypW.T + bypB
    gemm_proj_kernel<<<gemm_blocks, 128>>>(x, projW, projB, bypW, bypB, p_h0, p_byp, N);

    // layer 1: h1 = relu(bn(agg(h0 @ W1.T) + b1)) + h0
    gemm64h_kernel<<<gemm_blocks, 128>>>(p_h0, conv1W, p_tmp, N);
    agg_kernel<<<agg_blocks, 256>>>(p_tmp, p_csr, p_rowptr, p_dinv,
                                    conv1B, bn1g, bn1b, p_h0, p_h1,
                                    nullptr, nullptr, nullptr, nullptr, N, 0);

    // layer 2: h2 (stored in g_h0) = relu(bn(agg(h1 @ W2.T) + b2)) + h1
    gemm64h_kernel<<<gemm_blocks, 128>>>(p_h1, conv2W, p_tmp, N);
    agg_kernel<<<agg_blocks, 256>>>(p_tmp, p_csr, p_rowptr, p_dinv,
                                    conv2B, bn2g, bn2b, p_h1, p_h0,
                                    nullptr, nullptr, nullptr, nullptr, N, 0);

    // layer 3 + head fused -> out
    gemm64h_kernel<<<gemm_blocks, 128>>>(p_h0, conv3W, p_tmp, N);
    agg_kernel<<<agg_blocks, 256>>>(p_tmp, p_csr, p_rowptr, p_dinv,
                                    conv3B, bn3g, bn3b, nullptr, nullptr,
                                    headW, headB, p_byp, out, N, 1);
}

// round 8
// speedup vs baseline: 1.3414x; 1.0547x over previous
#include <cuda_runtime.h>
#include <cuda_fp16.h>
#include <cuda_bf16.h>

#define NMAX 100000
#define EMAX 1200000
#define CSRMAX (NMAX + EMAX)

// ---------------- scratch (device globals; no allocations allowed) ----------
__device__ float   g_h0[NMAX * 64];     // proj output / residual, later reused as h2
__device__ float   g_h1[NMAX * 64];     // layer1 output
__device__ __half2 g_tmp[NMAX * 32];    // W-transformed features (fp16 gather table)
__device__ float   g_byp[NMAX * 3];     // bypass projection
__device__ float   g_dinv[NMAX];
__device__ int     g_deg[NMAX];         // zero at start of every execution (fill re-zeroes)
__device__ int     g_rowptr[NMAX + 1];
__device__ int     g_cursor[NMAX];
__device__ float2  g_csr[CSRMAX];       // .x = src index (bit-cast), .y = dinv[src]
__device__ int     g_bsum[256];

// ---------------- f32x2 helpers -----------------------------------------------
__device__ __forceinline__ void ffma2(unsigned long long& d,
                                      unsigned long long a,
                                      unsigned long long b) {
    asm("fma.rn.f32x2 %0, %1, %2, %0;" : "+l"(d) : "l"(a), "l"(b));
}
__device__ __forceinline__ unsigned long long dup2(float x) {
    unsigned long long r;
    unsigned u = __float_as_uint(x);
    asm("mov.b64 %0, {%1, %1};" : "=l"(r) : "r"(u));
    return r;
}
__device__ __forceinline__ float lo32(unsigned long long v) {
    return __uint_as_float((unsigned)(v & 0xffffffffull));
}
__device__ __forceinline__ float hi32(unsigned long long v) {
    return __uint_as_float((unsigned)(v >> 32));
}

// ---------------- merged1: proj GEMM (+bypass) blocks || hist blocks --------
// blocks [0, PB): proj tile (64 rows); blocks [PB, PB+HB): histogram of col[].
__global__ void __launch_bounds__(128) merged1_kernel(
    const float* __restrict__ x, const float* __restrict__ Wp,
    const float* __restrict__ bp, const float* __restrict__ Wb,
    const float* __restrict__ bb, float* __restrict__ h0,
    float* __restrict__ byp, int N,
    const int* __restrict__ col, int* __restrict__ deg, int E, int PB)
{
    __shared__ float Xs[64][65];
    __shared__ float Ws[64][66];   // transposed per chunk: Ws[k][c]
    __shared__ float Bs[3][65];
    int tid = threadIdx.x;
    int bid = blockIdx.x;

    if (bid >= PB) {
        // ---- histogram: 1024 edges per block, 8 per thread ----
        int base = (bid - PB) * 1024;
#pragma unroll
        for (int j = 0; j < 8; ++j) {
            int e = base + j * 128 + tid;
            if (e < E) atomicAdd(&deg[col[e]], 1);
        }
        return;
    }

    int row0 = bid * 64;
    int tr  = tid >> 3;
    int tc2 = (tid & 7) * 2;

    unsigned long long acc[4][4];
    float bacc[4] = {0.f, 0.f, 0.f, 0.f};
#pragma unroll
    for (int i = 0; i < 4; ++i)
#pragma unroll
        for (int j = 0; j < 4; ++j) acc[i][j] = 0ull;

    for (int kc = 0; kc < 2; ++kc) {
        int kbase = kc * 64;
        for (int l = tid; l < 1024; l += 128) {
            int r = l >> 4, k4 = (l & 15) * 4;
            int n = row0 + r;
            float4 xv = make_float4(0.f, 0.f, 0.f, 0.f);
            if (n < N) xv = *(const float4*)(x + n * 128 + kbase + k4);
            Xs[r][k4] = xv.x; Xs[r][k4 + 1] = xv.y; Xs[r][k4 + 2] = xv.z; Xs[r][k4 + 3] = xv.w;
            float4 wv = *(const float4*)(Wp + r * 128 + kbase + k4);
            Ws[k4][r] = wv.x; Ws[k4 + 1][r] = wv.y; Ws[k4 + 2][r] = wv.z; Ws[k4 + 3][r] = wv.w;
        }
        for (int l = tid; l < 192; l += 128)
            Bs[l >> 6][l & 63] = Wb[(l >> 6) * 128 + kbase + (l & 63)];
        __syncthreads();

        int tc = tid & 7;
#pragma unroll 4
        for (int k = 0; k < 64; ++k) {
            float a_s[4];
            unsigned long long aa[4], wv[4];
#pragma unroll
            for (int i = 0; i < 4; ++i) { a_s[i] = Xs[tr + i * 16][k]; aa[i] = dup2(a_s[i]); }
#pragma unroll
            for (int j = 0; j < 4; ++j)
                wv[j] = *(const unsigned long long*)&Ws[k][tc2 + 16 * j];
#pragma unroll
            for (int i = 0; i < 4; ++i)
#pragma unroll
                for (int j = 0; j < 4; ++j) ffma2(acc[i][j], aa[i], wv[j]);
            if (tc < 3) {
                float bw = Bs[tc][k];
#pragma unroll
                for (int i = 0; i < 4; ++i) bacc[i] = fmaf(a_s[i], bw, bacc[i]);
            }
        }
        __syncthreads();
    }

    int tc = tid & 7;
#pragma unroll
    for (int i = 0; i < 4; ++i) {
        int n = row0 + tr + i * 16;
        if (n < N) {
#pragma unroll
            for (int j = 0; j < 4; ++j) {
                int c = tc2 + 16 * j;
                float2 v;
                v.x = lo32(acc[i][j]) + bp[c];
                v.y = hi32(acc[i][j]) + bp[c + 1];
                *(float2*)(h0 + n * 64 + c) = v;
            }
            if (tc < 3) byp[n * 3 + tc] = bacc[i] + bb[tc];
        }
    }
}

// ---------------- merged2: conv1 GEMM blocks || scan1 blocks ----------------
// blocks [0, GB): 64x64 GEMM h0@W1.T -> fp16 tmp; blocks [GB, GB+SB): scan1.
// scan1 block s: 1024 nodes, 8 per thread; rowptr[i] = block-local exclusive
// prefix of (deg[i]+1); bsum[s] = block total.
__global__ void __launch_bounds__(128) merged2_kernel(
    const float* __restrict__ A, const float* __restrict__ W,
    __half2* __restrict__ out, int N,
    const int* __restrict__ deg, int* __restrict__ rowptr,
    int* __restrict__ bsum, int GB)
{
    __shared__ float Xs[64][65];
    __shared__ float Ws[64][66];   // transposed: Ws[k][c]
    __shared__ int sc[128];
    int tid = threadIdx.x;
    int bid = blockIdx.x;

    if (bid >= GB) {
        int sb = bid - GB;
        int i0 = sb * 1024 + tid * 8;
        int dl[8];
        int s = 0;
#pragma unroll
        for (int j = 0; j < 8; ++j) {
            int i = i0 + j;
            int dd = (i < N) ? (deg[i] + 1) : 0;
            dl[j] = s;       // exclusive within thread
            s += dd;
        }
        sc[tid] = s;
        __syncthreads();
        for (int off = 1; off < 128; off <<= 1) {
            int u = (tid >= off) ? sc[tid - off] : 0;
            __syncthreads();
            sc[tid] += u;
            __syncthreads();
        }
        int excl = tid ? sc[tid - 1] : 0;
#pragma unroll
        for (int j = 0; j < 8; ++j) {
            int i = i0 + j;
            if (i < N) rowptr[i] = excl + dl[j];
        }
        if (tid == 127) bsum[sb] = sc[127];
        return;
    }

    int row0 = bid * 64;
    int tr  = tid >> 3;
    int tc2 = (tid & 7) * 2;

    for (int l = tid; l < 1024; l += 128) {
        int r = l >> 4, k4 = (l & 15) * 4;
        int n = row0 + r;
        float4 xv = make_float4(0.f, 0.f, 0.f, 0.f);
        if (n < N) xv = *(const float4*)(A + n * 64 + k4);
        Xs[r][k4] = xv.x; Xs[r][k4 + 1] = xv.y; Xs[r][k4 + 2] = xv.z; Xs[r][k4 + 3] = xv.w;
        float4 wv = *(const float4*)(W + r * 64 + k4);
        Ws[k4][r] = wv.x; Ws[k4 + 1][r] = wv.y; Ws[k4 + 2][r] = wv.z; Ws[k4 + 3][r] = wv.w;
    }
    __syncthreads();

    unsigned long long acc[4][4];
#pragma unroll
    for (int i = 0; i < 4; ++i)
#pragma unroll
        for (int j = 0; j < 4; ++j) acc[i][j] = 0ull;

#pragma unroll 4
    for (int k = 0; k < 64; ++k) {
        unsigned long long aa[4], wv[4];
#pragma unroll
        for (int i = 0; i < 4; ++i) aa[i] = dup2(Xs[tr + i * 16][k]);
#pragma unroll
        for (int j = 0; j < 4; ++j)
            wv[j] = *(const unsigned long long*)&Ws[k][tc2 + 16 * j];
#pragma unroll
        for (int i = 0; i < 4; ++i)
#pragma unroll
            for (int j = 0; j < 4; ++j) ffma2(acc[i][j], aa[i], wv[j]);
    }

#pragma unroll
    for (int i = 0; i < 4; ++i) {
        int n = row0 + tr + i * 16;
        if (n < N) {
#pragma unroll
            for (int j = 0; j < 4; ++j) {
                float2 v = make_float2(lo32(acc[i][j]), hi32(acc[i][j]));
                out[n * 32 + (tc2 >> 1) + 8 * j] = __float22half2_rn(v);
            }
        }
    }
}

// ---------------- plain 64x64 GEMM (layers 2/3) -----------------------------
__global__ void __launch_bounds__(128) gemm64h_kernel(
    const float* __restrict__ A, const float* __restrict__ W,
    __half2* __restrict__ out, int N)
{
    __shared__ float Xs[64][65];
    __shared__ float Ws[64][66];
    int tid = threadIdx.x;
    int row0 = blockIdx.x * 64;
    int tr  = tid >> 3;
    int tc2 = (tid & 7) * 2;

    for (int l = tid; l < 1024; l += 128) {
        int r = l >> 4, k4 = (l & 15) * 4;
        int n = row0 + r;
        float4 xv = make_float4(0.f, 0.f, 0.f, 0.f);
        if (n < N) xv = *(const float4*)(A + n * 64 + k4);
        Xs[r][k4] = xv.x; Xs[r][k4 + 1] = xv.y; Xs[r][k4 + 2] = xv.z; Xs[r][k4 + 3] = xv.w;
        float4 wv = *(const float4*)(W + r * 64 + k4);
        Ws[k4][r] = wv.x; Ws[k4 + 1][r] = wv.y; Ws[k4 + 2][r] = wv.z; Ws[k4 + 3][r] = wv.w;
    }
    __syncthreads();

    unsigned long long acc[4][4];
#pragma unroll
    for (int i = 0; i < 4; ++i)
#pragma unroll
        for (int j = 0; j < 4; ++j) acc[i][j] = 0ull;

#pragma unroll 4
    for (int k = 0; k < 64; ++k) {
        unsigned long long aa[4], wv[4];
#pragma unroll
        for (int i = 0; i < 4; ++i) aa[i] = dup2(Xs[tr + i * 16][k]);
#pragma unroll
        for (int j = 0; j < 4; ++j)
            wv[j] = *(const unsigned long long*)&Ws[k][tc2 + 16 * j];
#pragma unroll
        for (int i = 0; i < 4; ++i)
#pragma unroll
            for (int j = 0; j < 4; ++j) ffma2(acc[i][j], aa[i], wv[j]);
    }

#pragma unroll
    for (int i = 0; i < 4; ++i) {
        int n = row0 + tr + i * 16;
        if (n < N) {
#pragma unroll
            for (int j = 0; j < 4; ++j) {
                float2 v = make_float2(lo32(acc[i][j]), hi32(acc[i][j]));
                out[n * 32 + (tc2 >> 1) + 8 * j] = __float22half2_rn(v);
            }
        }
    }
}

// ---------------- scan3 (with inline scan of block sums) --------------------
__global__ void __launch_bounds__(256) scan3_kernel(
    const int* __restrict__ deg, int* rowptr,
    const int* __restrict__ bsum, int* cursor,
    float* dinv, float2* csr, int N, int nb)
{
    __shared__ int sm[128];
    int tid = threadIdx.x;
    if (tid < 128) sm[tid] = (tid < nb) ? bsum[tid] : 0;
    __syncthreads();
    for (int off = 1; off < 128; off <<= 1) {
        int u = 0;
        if (tid < 128 && tid >= off) u = sm[tid - off];
        __syncthreads();
        if (tid < 128) sm[tid] += u;
        __syncthreads();
    }
    int myb = blockIdx.x >> 2;           // 256-node block -> 1024-node scan1 block
    int pref = myb ? sm[myb - 1] : 0;

    int i = blockIdx.x * 256 + tid;
    if (i >= N) return;
    int dtot = deg[i] + 1;               // +1 = self-loop
    int rp = rowptr[i] + pref;
    rowptr[i] = rp;
    cursor[i] = rp + 1;                  // slot rp reserved for self-loop
    float dv = rsqrtf((float)dtot);
    dinv[i] = dv;
    csr[rp] = make_float2(__int_as_float(i), dv);
    if (i == N - 1) rowptr[N] = rp + dtot;
}

// ---------------- fill (also re-zeroes deg for the next execution) ----------
__global__ void fill_kernel(const int* __restrict__ row, const int* __restrict__ col,
                            const float* __restrict__ dinv, int* cursor,
                            float2* csr, int* __restrict__ deg, int E, int N) {
    int e = blockIdx.x * blockDim.x + threadIdx.x;
    if (e < N) deg[e] = 0;               // deg consumed by scan3; reset for next call
    if (e >= E) return;
    int d = col[e];
    int pos = atomicAdd(&cursor[d], 1);
    int s = row[e];
    csr[pos] = make_float2(__int_as_float(s), dinv[s]);
}

// ---------------- aggregation (warp per node, half-warp per edge stream) ----
__global__ void __launch_bounds__(256) agg_kernel(
    const __half2* __restrict__ tmp, const float2* __restrict__ csr,
    const int* __restrict__ rowptr, const float* __restrict__ dinv,
    const float* __restrict__ convb, const float* __restrict__ bng,
    const float* __restrict__ bnb, const float* __restrict__ resid,
    float* __restrict__ outh, const float* __restrict__ headW,
    const float* __restrict__ headb, const float* __restrict__ byp,
    float* __restrict__ out, int N, int mode)
{
    int gt = blockIdx.x * blockDim.x + threadIdx.x;
    int v = gt >> 5;
    int lane = gt & 31;
    if (v >= N) return;
    int half = lane >> 4;
    int sub  = lane & 15;

    const uint2* hp = (const uint2*)tmp;
    int s = rowptr[v];
    int e = rowptr[v + 1];

    float a0 = 0.f, a1 = 0.f, a2 = 0.f, a3 = 0.f;
    int p = s + half;
    for (; p + 2 < e; p += 4) {
        float2 e0 = csr[p];
        float2 e1 = csr[p + 2];
        int s0 = __float_as_int(e0.x);
        int s1 = __float_as_int(e1.x);
        uint2 r0 = hp[s0 * 16 + sub];
        uint2 r1 = hp[s1 * 16 + sub];
        float2 f00 = __half22float2(*(__half2*)&r0.x);
        float2 f01 = __half22float2(*(__half2*)&r0.y);
        float2 f10 = __half22float2(*(__half2*)&r1.x);
        float2 f11 = __half22float2(*(__half2*)&r1.y);
        a0 = fmaf(e0.y, f00.x, a0); a1 = fmaf(e0.y, f00.y, a1);
        a2 = fmaf(e0.y, f01.x, a2); a3 = fmaf(e0.y, f01.y, a3);
        a0 = fmaf(e1.y, f10.x, a0); a1 = fmaf(e1.y, f10.y, a1);
        a2 = fmaf(e1.y, f11.x, a2); a3 = fmaf(e1.y, f11.y, a3);
    }
    if (p < e) {
        float2 e0 = csr[p];
        int s0 = __float_as_int(e0.x);
        uint2 r0 = hp[s0 * 16 + sub];
        float2 f00 = __half22float2(*(__half2*)&r0.x);
        float2 f01 = __half22float2(*(__half2*)&r0.y);
        a0 = fmaf(e0.y, f00.x, a0); a1 = fmaf(e0.y, f00.y, a1);
        a2 = fmaf(e0.y, f01.x, a2); a3 = fmaf(e0.y, f01.y, a3);
    }
    a0 += __shfl_xor_sync(0xffffffffu, a0, 16);
    a1 += __shfl_xor_sync(0xffffffffu, a1, 16);
    a2 += __shfl_xor_sync(0xffffffffu, a2, 16);
    a3 += __shfl_xor_sync(0xffffffffu, a3, 16);

    float dv = dinv[v];
    const float bninv = rsqrtf(1.0f + 1e-5f);

    if (mode == 0) {
        if (half == 0) {
            int c = sub * 4;
            float4 cb = *(const float4*)(convb + c);
            float4 bg = *(const float4*)(bng + c);
            float4 bo = *(const float4*)(bnb + c);
            float4 r  = *(const float4*)(resid + v * 64 + c);
            float4 o;
            o.x = fmaxf(fmaf(fmaf(a0, dv, cb.x), bg.x * bninv, bo.x), 0.f) + r.x;
            o.y = fmaxf(fmaf(fmaf(a1, dv, cb.y), bg.y * bninv, bo.y), 0.f) + r.y;
            o.z = fmaxf(fmaf(fmaf(a2, dv, cb.z), bg.z * bninv, bo.z), 0.f) + r.z;
            o.w = fmaxf(fmaf(fmaf(a3, dv, cb.w), bg.w * bninv, bo.w), 0.f) + r.w;
            *(float4*)(outh + v * 64 + c) = o;
        }
    } else {
        float p0 = 0.f, p1 = 0.f, p2 = 0.f;
        if (half == 0) {
            int c = sub * 4;
            float4 cb = *(const float4*)(convb + c);
            float4 bg = *(const float4*)(bng + c);
            float4 bo = *(const float4*)(bnb + c);
            float v0 = fmaxf(fmaf(fmaf(a0, dv, cb.x), bg.x * bninv, bo.x), 0.f);
            float v1 = fmaxf(fmaf(fmaf(a1, dv, cb.y), bg.y * bninv, bo.y), 0.f);
            float v2 = fmaxf(fmaf(fmaf(a2, dv, cb.z), bg.z * bninv, bo.z), 0.f);
            float v3 = fmaxf(fmaf(fmaf(a3, dv, cb.w), bg.w * bninv, bo.w), 0.f);
            p0 = v0 * headW[c]       + v1 * headW[c + 1]       + v2 * headW[c + 2]       + v3 * headW[c + 3];
            p1 = v0 * headW[67 + c]  + v1 * headW[67 + c + 1]  + v2 * headW[67 + c + 2]  + v3 * headW[67 + c + 3];
            p2 = v0 * headW[134 + c] + v1 * headW[134 + c + 1] + v2 * headW[134 + c + 2] + v3 * headW[134 + c + 3];
        }
#pragma unroll
        for (int o = 8; o > 0; o >>= 1) {
            p0 += __shfl_xor_sync(0xffffffffu, p0, o);
            p1 += __shfl_xor_sync(0xffffffffu, p1, o);
            p2 += __shfl_xor_sync(0xffffffffu, p2, o);
        }
        if (lane == 0) {
            float b0 = byp[v * 3], b1 = byp[v * 3 + 1], b2 = byp[v * 3 + 2];
            p0 += headW[64] * b0 + headW[65] * b1 + headW[66] * b2 + headb[0];
            p1 += headW[67 + 64] * b0 + headW[67 + 65] * b1 + headW[67 + 66] * b2 + headb[1];
            p2 += headW[134 + 64] * b0 + headW[134 + 65] * b1 + headW[134 + 66] * b2 + headb[2];
            float kappa = fminf(fmaxf(p0 * 5.f + 2.5f, 0.2f), 10.f);
            float tau   = fminf(fmaxf(p2 + 0.5f, 0.05f), 2.f);
            out[v * 3]     = kappa;
            out[v * 3 + 1] = p1;
            out[v * 3 + 2] = tau;
        }
    }
}

// ---------------- launch -----------------------------------------------------
extern "C" void kernel_launch(void* const* d_in, const int* in_sizes, int n_in,
                              void* d_out, int out_size) {
    const float* x      = (const float*)d_in[0];
    const int*   ei     = (const int*)d_in[1];
    const float* projW  = (const float*)d_in[2];
    const float* projB  = (const float*)d_in[3];
    const float* conv1W = (const float*)d_in[4];
    const float* conv1B = (const float*)d_in[5];
    const float* bn1g   = (const float*)d_in[6];
    const float* bn1b   = (const float*)d_in[7];
    const float* conv2W = (const float*)d_in[8];
    const float* conv2B = (const float*)d_in[9];
    const float* bn2g   = (const float*)d_in[10];
    const float* bn2b   = (const float*)d_in[11];
    const float* conv3W = (const float*)d_in[12];
    const float* conv3B = (const float*)d_in[13];
    const float* bn3g   = (const float*)d_in[14];
    const float* bn3b   = (const float*)d_in[15];
    const float* bypW   = (const float*)d_in[16];
    const float* bypB   = (const float*)d_in[17];
    const float* headW  = (const float*)d_in[18];
    const float* headB  = (const float*)d_in[19];
    float* out = (float*)d_out;

    int N = in_sizes[0] / 128;
    int E = in_sizes[1] / 2;
    const int* row = ei;
    const int* col = ei + E;

    float *p_h0, *p_h1, *p_byp, *p_dinv;
    __half2* p_tmp;
    int *p_deg, *p_rowptr, *p_cursor, *p_bsum;
    float2* p_csr;
    cudaGetSymbolAddress((void**)&p_h0, g_h0);
    cudaGetSymbolAddress((void**)&p_h1, g_h1);
    cudaGetSymbolAddress((void**)&p_tmp, g_tmp);
    cudaGetSymbolAddress((void**)&p_byp, g_byp);
    cudaGetSymbolAddress((void**)&p_dinv, g_dinv);
    cudaGetSymbolAddress((void**)&p_deg, g_deg);
    cudaGetSymbolAddress((void**)&p_rowptr, g_rowptr);
    cudaGetSymbolAddress((void**)&p_cursor, g_cursor);
    cudaGetSymbolAddress((void**)&p_bsum, g_bsum);
    cudaGetSymbolAddress((void**)&p_csr, g_csr);

    int PB = (N + 63) / 64;              // proj / gemm blocks
    int HB = (E + 1023) / 1024;          // hist blocks (1024 edges each)
    int SB = (N + 1023) / 1024;          // scan1 blocks
    int agg_blocks = (N * 32 + 255) / 256;

    // K1: proj GEMM (+bypass)  ||  degree histogram
    merged1_kernel<<<PB + HB, 128>>>(x, projW, projB, bypW, bypB, p_h0, p_byp, N,
                                     col, p_deg, E, PB);

    // K2: conv1 GEMM -> fp16 tmp  ||  scan1 (block-local prefix + block sums)
    merged2_kernel<<<PB + SB, 128>>>(p_h0, conv1W, p_tmp, N,
                                     p_deg, p_rowptr, p_bsum, PB);

    // K3: scan3 (inline scan of bsum) -> rowptr/cursor/dinv/self-loops
    scan3_kernel<<<(N + 255) / 256, 256>>>(p_deg, p_rowptr, p_bsum, p_cursor,
                                           p_dinv, p_csr, N, SB);

    // K4: CSR fill (+ re-zero deg for next execution)
    fill_kernel<<<(E + 255) / 256, 256>>>(row, col, p_dinv, p_cursor, p_csr,
                                          p_deg, E, N);

    // K5: layer-1 aggregation
    agg_kernel<<<agg_blocks, 256>>>(p_tmp, p_csr, p_rowptr, p_dinv,
                                    conv1B, bn1g, bn1b, p_h0, p_h1,
                                    nullptr, nullptr, nullptr, nullptr, N, 0);

    // K6/K7: layer 2
    gemm64h_kernel<<<PB, 128>>>(p_h1, conv2W, p_tmp, N);
    agg_kernel<<<agg_blocks, 256>>>(p_tmp, p_csr, p_rowptr, p_dinv,
                                    conv2B, bn2g, bn2b, p_h1, p_h0,
                                    nullptr, nullptr, nullptr, nullptr, N, 0);

    // K8/K9: layer 3 + head fused
    gemm64h_kernel<<<PB, 128>>>(p_h0, conv3W, p_tmp, N);
    agg_kernel<<<agg_blocks, 256>>>(p_tmp, p_csr, p_rowptr, p_dinv,
                                    conv3B, bn3g, bn3b, nullptr, nullptr,
                                    headW, headB, p_byp, out, N, 1);
}